// round 17
// baseline (speedup 1.0000x reference)
#include <cuda_runtime.h>
#include <cuda_fp16.h>
#include <cstdint>

// ===========================================================================
// Encoder (single-head attention, d=1024, batch 8, seq 2048).
// Plain sm_100 target -> ldmatrix + mma.sync.m16n8k16 fp16 (fp32 accum).
// R16/R17: fully 1-term fp16 pipeline (R15 numerics, rel_err 5.5e-4) with a
// BIGGER WARPTILE to fix the LDSM-bound profile (tensor 57.8%, L1 54.4%):
//   warptile 64x64 (acc 128 regs), CTA tile 128x256, 8 warps (2x4),
//   1 CTA/SM (launch_bounds(256,1), ~190 live regs), GBK=64,
//   3-stage cp.async (48KB/stage, 144KB smem). MMA:LDSM 2.67 -> 4.
// 128B rows; swizzle col16' = col16 ^ (row&7) (R8-proven, conflict-free).
// ===========================================================================

#define BATCH   8
#define SEQ     2048
#define DMODEL  1024
#define MTOT    (BATCH * SEQ)

typedef __half fp16;

// ---- static device scratch ------------------------------------------------
__device__ fp16 g_xh  [MTOT * DMODEL];
__device__ fp16 g_wh  [4][DMODEL * DMODEL];   // q,k,v,o single fp16
__device__ fp16 g_Qh  [MTOT * DMODEL];
__device__ fp16 g_Kh  [MTOT * DMODEL];
__device__ fp16 g_Vh  [MTOT * DMODEL];
__device__ fp16 g_Vth [MTOT * DMODEL];
__device__ float g_S  [(size_t)BATCH * SEQ * SEQ];
__device__ fp16 g_Ph  [(size_t)BATCH * SEQ * SEQ];
__device__ fp16 g_Ch  [MTOT * DMODEL];

// ---- PTX helpers ----------------------------------------------------------
__device__ __forceinline__ uint32_t smem_u32(const void* p) {
    uint32_t a;
    asm("{ .reg .u64 t; cvta.to.shared.u64 t, %1; cvt.u32.u64 %0, t; }"
        : "=r"(a) : "l"(p));
    return a;
}

__device__ __forceinline__ void cp_async16(uint32_t dst, const void* src) {
    asm volatile("cp.async.cg.shared.global [%0], [%1], 16;"
                 :: "r"(dst), "l"(src) : "memory");
}
#define CP_COMMIT() asm volatile("cp.async.commit_group;" ::: "memory")
#define CP_WAIT1()  asm volatile("cp.async.wait_group 1;"  ::: "memory")
#define CP_WAIT0()  asm volatile("cp.async.wait_group 0;"  ::: "memory")

__device__ __forceinline__ void ldm_x4(uint32_t* r, uint32_t addr) {
    asm volatile("ldmatrix.sync.aligned.m8n8.x4.shared.b16 {%0,%1,%2,%3}, [%4];"
                 : "=r"(r[0]), "=r"(r[1]), "=r"(r[2]), "=r"(r[3]) : "r"(addr));
}

__device__ __forceinline__ void mma16816(float* d, const uint32_t* a,
                                         uint32_t b0, uint32_t b1) {
    asm volatile("mma.sync.aligned.m16n8k16.row.col.f32.f16.f16.f32 "
                 "{%0,%1,%2,%3}, {%4,%5,%6,%7}, {%8,%9}, {%0,%1,%2,%3};"
                 : "+f"(d[0]), "+f"(d[1]), "+f"(d[2]), "+f"(d[3])
                 : "r"(a[0]), "r"(a[1]), "r"(a[2]), "r"(a[3]), "r"(b0), "r"(b1));
}

__device__ __forceinline__ uint32_t pack2h(fp16 a, fp16 b) {
    __half2 t; t.x = a; t.y = b;
    return *reinterpret_cast<uint32_t*>(&t);
}

// ---------------------------------------------------------------------------
// hgemm<OUTMODE>: C[M,N] = alpha * A[M,K] * B[N,K]^T, A,B single fp16.
//   OUTMODE 0: fp32 C (alpha applied).  OUTMODE 2: single fp16 C.
// CTA tile 128x256x64, 256 threads, 8 warps (wm=wid&1 x2, wn=wid>>1 x4),
// warptile 64x64 (acc 128 regs). 3-stage cp.async, 48KB/stage, 1 CTA/SM.
// 128B rows; swizzle col16' = col16 ^ (row&7).
// ---------------------------------------------------------------------------
#define GBK 64
#define STAGE_BYTES 49152
#define T_B 16384
#define HG_SMEM (3 * STAGE_BYTES)

template <int OUTMODE>
__global__ __launch_bounds__(256, 1)
void hgemm(const fp16* __restrict__ A, const fp16* __restrict__ B,
           float* __restrict__ Cf, fp16* __restrict__ Ch,
           int K, int ldC, float alpha,
           size_t strA, size_t strB, size_t strC)
{
    extern __shared__ __align__(128) char smem[];
    const uint32_t sb = smem_u32(smem);

    const int tid  = threadIdx.x;
    const int lane = tid & 31;
    const int wid  = tid >> 5;
    const int wm   = wid & 1;           // 2 warp rows (M, 64 each)
    const int wn   = wid >> 1;          // 4 warp cols (N, 64 each)

    const size_t bz = blockIdx.z;
    A += bz * strA;
    B += bz * strB;
    const int row0 = blockIdx.y * 128;
    const int col0 = blockIdx.x * 256;

    // A: 128 rows x 8 c16 chunks = 1024; B: 256 rows x 8 = 2048.
    auto load_stage = [&](int s, int kiter) {
        const int k0 = kiter * GBK;
        const uint32_t stb = sb + s * STAGE_BYTES;
#pragma unroll
        for (int i = 0; i < 4; i++) {           // A chunks
            const int c    = tid + i * 256;
            const int row  = c >> 3;            // 0..127
            const int c16  = c & 7;             // 0..7
            const uint32_t soff =
                (uint32_t)(row * 128 + (((c16 ^ row) & 7) << 4));
            cp_async16(stb + soff,
                       A + (size_t)(row0 + row) * K + k0 + c16 * 8);
        }
#pragma unroll
        for (int i = 0; i < 8; i++) {           // B chunks
            const int c    = tid + i * 256;
            const int row  = c >> 3;            // 0..255
            const int c16  = c & 7;
            const uint32_t soff =
                (uint32_t)(row * 128 + (((c16 ^ row) & 7) << 4));
            cp_async16(stb + T_B + soff,
                       B + (size_t)(col0 + row) * K + k0 + c16 * 8);
        }
    };

    const int lr16 = lane & 15;
    const int lhi  = lane >> 4;
    int arow[4], brow[4];
#pragma unroll
    for (int mt = 0; mt < 4; mt++) arow[mt] = wm * 64 + mt * 16 + lr16;
#pragma unroll
    for (int np = 0; np < 4; np++) brow[np] = wn * 64 + np * 16 + lr16;

    auto smaddr = [&](int row, int cb) -> uint32_t {
        return (uint32_t)(row * 128 + (((cb ^ row) & 7) << 4));
    };

    float acc[4][8][4];
#pragma unroll
    for (int a = 0; a < 4; a++)
#pragma unroll
        for (int b = 0; b < 8; b++)
#pragma unroll
            for (int r = 0; r < 4; r++) acc[a][b][r] = 0.f;

    const int niter = K / GBK;

    load_stage(0, 0); CP_COMMIT();
    load_stage(1, 1); CP_COMMIT();
    CP_WAIT1();
    __syncthreads();

    int s = 0, pf = 2;
    for (int it = 0; it < niter; ++it) {
        const uint32_t stb = sb + s * STAGE_BYTES;
#pragma unroll
        for (int kk = 0; kk < 4; kk++) {
            const int cb = kk * 2 + lhi;        // 0..7
            uint32_t a[4][4], b[4][4];
#pragma unroll
            for (int mt = 0; mt < 4; mt++)
                ldm_x4(a[mt], stb + smaddr(arow[mt], cb));
#pragma unroll
            for (int np = 0; np < 4; np++)
                ldm_x4(b[np], stb + T_B + smaddr(brow[np], cb));
#pragma unroll
            for (int np = 0; np < 4; np++)
#pragma unroll
                for (int mt = 0; mt < 4; mt++)
#pragma unroll
                    for (int sub = 0; sub < 2; sub++)
                        mma16816(acc[mt][np * 2 + sub], a[mt],
                                 b[np][sub], b[np][sub + 2]);
        }
        if (it + 2 < niter) {
            load_stage(pf, it + 2);
            CP_COMMIT();
            CP_WAIT1();
        } else {
            CP_WAIT0();
        }
        __syncthreads();
        s  = (s  == 2) ? 0 : s  + 1;
        pf = (pf == 2) ? 0 : pf + 1;
    }

    const int gi = lane >> 2;
    const int ti = lane & 3;
#pragma unroll
    for (int mt = 0; mt < 4; mt++) {
#pragma unroll
        for (int nt = 0; nt < 8; nt++) {
            const int col = col0 + wn * 64 + nt * 8 + ti * 2;
#pragma unroll
            for (int h = 0; h < 2; h++) {
                const size_t row = row0 + wm * 64 + mt * 16 + gi + h * 8;
                const float v0 = acc[mt][nt][h * 2 + 0] * alpha;
                const float v1 = acc[mt][nt][h * 2 + 1] * alpha;
                const size_t off = (strC * bz) + row * ldC + col;
                if (OUTMODE == 0) {
                    float2 f2; f2.x = v0; f2.y = v1;
                    *reinterpret_cast<float2*>(Cf + off) = f2;
                } else {
                    *reinterpret_cast<uint32_t*>(Ch + off) =
                        pack2h(__float2half_rn(v0), __float2half_rn(v1));
                }
            }
        }
    }
}

// ---------------------------------------------------------------------------
// conv: fp32 -> single fp16 (4 elems/thread)
// ---------------------------------------------------------------------------
__global__ __launch_bounds__(256)
void conv_kernel(const float* __restrict__ src, fp16* __restrict__ dst, int n4)
{
    const int i = blockIdx.x * 256 + threadIdx.x;
    if (i >= n4) return;
    float4 v = reinterpret_cast<const float4*>(src)[i];
    uint2 ph;
    ph.x = pack2h(__float2half_rn(v.x), __float2half_rn(v.y));
    ph.y = pack2h(__float2half_rn(v.z), __float2half_rn(v.w));
    reinterpret_cast<uint2*>(dst)[i] = ph;
}

// weights: fp32 -> single fp16, all 4 in one launch (grid.z selects)
struct WPtrs { const float* src[4]; fp16* h; };
__global__ __launch_bounds__(256)
void conv_w_kernel(WPtrs p, int n4)
{
    const int z = blockIdx.z;
    const int i = blockIdx.x * 256 + threadIdx.x;
    if (i >= n4) return;
    const size_t wstr = (size_t)DMODEL * DMODEL / 4;   // in uint2 units
    float4 v = reinterpret_cast<const float4*>(p.src[z])[i];
    uint2 ph;
    ph.x = pack2h(__float2half_rn(v.x), __float2half_rn(v.y));
    ph.y = pack2h(__float2half_rn(v.z), __float2half_rn(v.w));
    reinterpret_cast<uint2*>(p.h)[z * wstr + i] = ph;
}

// ---------------------------------------------------------------------------
// fp16 transpose per batch: dst[v][s] = src[s][v]
// ---------------------------------------------------------------------------
__global__ __launch_bounds__(256)
void transpose_h(const fp16* __restrict__ src, fp16* __restrict__ dst)
{
    __shared__ fp16 t[32][33];
    const fp16* s = src + (size_t)blockIdx.z * SEQ * DMODEL;
    fp16*       o = dst + (size_t)blockIdx.z * SEQ * DMODEL;
    const int s0 = blockIdx.x * 32;
    const int v0 = blockIdx.y * 32;
    const int tx = threadIdx.x & 31, ty = threadIdx.x >> 5;
#pragma unroll
    for (int r = 0; r < 4; r++)
        t[ty + r * 8][tx] = s[(size_t)(s0 + ty + r * 8) * DMODEL + v0 + tx];
    __syncthreads();
#pragma unroll
    for (int r = 0; r < 4; r++)
        o[(size_t)(v0 + ty + r * 8) * SEQ + s0 + tx] = t[tx][ty + r * 8];
}

// ---------------------------------------------------------------------------
// softmax row (2048) fp32 -> P single fp16
// ---------------------------------------------------------------------------
__global__ __launch_bounds__(256)
void softmax_kernel(const float* __restrict__ S, fp16* __restrict__ Ph)
{
    const size_t r0 = (size_t)blockIdx.x * SEQ;
    const float* row = S + r0;
    const int tid = threadIdx.x;

    float4 v0 = reinterpret_cast<const float4*>(row)[tid];
    float4 v1 = reinterpret_cast<const float4*>(row)[tid + 256];

    float m = fmaxf(fmaxf(fmaxf(v0.x, v0.y), fmaxf(v0.z, v0.w)),
                    fmaxf(fmaxf(v1.x, v1.y), fmaxf(v1.z, v1.w)));
    __shared__ float red[8];
#pragma unroll
    for (int o = 16; o > 0; o >>= 1)
        m = fmaxf(m, __shfl_xor_sync(0xffffffffu, m, o));
    if ((tid & 31) == 0) red[tid >> 5] = m;
    __syncthreads();
    m = red[0];
#pragma unroll
    for (int w = 1; w < 8; w++) m = fmaxf(m, red[w]);
    __syncthreads();

    v0.x = __expf(v0.x - m); v0.y = __expf(v0.y - m);
    v0.z = __expf(v0.z - m); v0.w = __expf(v0.w - m);
    v1.x = __expf(v1.x - m); v1.y = __expf(v1.y - m);
    v1.z = __expf(v1.z - m); v1.w = __expf(v1.w - m);

    float sum = (v0.x + v0.y + v0.z + v0.w) + (v1.x + v1.y + v1.z + v1.w);
#pragma unroll
    for (int o = 16; o > 0; o >>= 1)
        sum += __shfl_xor_sync(0xffffffffu, sum, o);
    if ((tid & 31) == 0) red[tid >> 5] = sum;
    __syncthreads();
    sum = red[0];
#pragma unroll
    for (int w = 1; w < 8; w++) sum += red[w];
    const float inv = 1.0f / sum;

    auto emit = [&](float4 v, int idx) {
        uint2 ph;
        ph.x = pack2h(__float2half_rn(v.x * inv), __float2half_rn(v.y * inv));
        ph.y = pack2h(__float2half_rn(v.z * inv), __float2half_rn(v.w * inv));
        reinterpret_cast<uint2*>(Ph + r0)[idx] = ph;
    };
    emit(v0, tid);
    emit(v1, tid + 256);
}

// ---------------------------------------------------------------------------
// Launch
// ---------------------------------------------------------------------------
extern "C" void kernel_launch(void* const* d_in, const int* in_sizes, int n_in,
                              void* d_out, int out_size)
{
    const float* x  = (const float*)d_in[0];
    float* out = (float*)d_out;

    fp16 *xh, *wh, *Qh, *Kh, *Vh, *Vth, *Ph, *Ch;
    float* S;
    cudaGetSymbolAddress((void**)&xh,  g_xh);
    cudaGetSymbolAddress((void**)&wh,  g_wh);
    cudaGetSymbolAddress((void**)&Qh,  g_Qh);
    cudaGetSymbolAddress((void**)&Kh,  g_Kh);
    cudaGetSymbolAddress((void**)&Vh,  g_Vh);
    cudaGetSymbolAddress((void**)&Vth, g_Vth);
    cudaGetSymbolAddress((void**)&S,   g_S);
    cudaGetSymbolAddress((void**)&Ph,  g_Ph);
    cudaGetSymbolAddress((void**)&Ch,  g_Ch);

    cudaFuncSetAttribute(hgemm<0>, cudaFuncAttributeMaxDynamicSharedMemorySize, HG_SMEM);
    cudaFuncSetAttribute(hgemm<2>, cudaFuncAttributeMaxDynamicSharedMemorySize, HG_SMEM);

    const dim3 blk(256);
    const size_t WSTR = (size_t)DMODEL * DMODEL;

    // #0: convert x -> single fp16
    conv_kernel<<<MTOT * DMODEL / 1024, blk>>>(x, xh, MTOT * DMODEL / 4);

    // #1: convert all 4 weights -> single fp16
    {
        WPtrs p;
        p.src[0] = (const float*)d_in[1];
        p.src[1] = (const float*)d_in[2];
        p.src[2] = (const float*)d_in[3];
        p.src[3] = (const float*)d_in[4];
        p.h = wh;
        dim3 g(DMODEL * DMODEL / 1024, 1, 4);
        conv_w_kernel<<<g, blk>>>(p, DMODEL * DMODEL / 4);
    }

    // #2-#4: projections -> single fp16 Q/K/V  (N tile 256)
    {
        dim3 grid(DMODEL / 256, MTOT / 128, 1);
        hgemm<2><<<grid, blk, HG_SMEM>>>(xh, wh + 0 * WSTR, nullptr, Qh,
                                         DMODEL, DMODEL, 1.f, 0, 0, 0);
        hgemm<2><<<grid, blk, HG_SMEM>>>(xh, wh + 1 * WSTR, nullptr, Kh,
                                         DMODEL, DMODEL, 1.f, 0, 0, 0);
        hgemm<2><<<grid, blk, HG_SMEM>>>(xh, wh + 2 * WSTR, nullptr, Vh,
                                         DMODEL, DMODEL, 1.f, 0, 0, 0);
    }

    // #5: S = Q K^T / 32 (fp32)
    {
        dim3 grid(SEQ / 256, SEQ / 128, BATCH);
        hgemm<0><<<grid, blk, HG_SMEM>>>(Qh, Kh, S, nullptr,
                                         DMODEL, SEQ, 0.03125f,
                                         (size_t)SEQ * DMODEL,
                                         (size_t)SEQ * DMODEL,
                                         (size_t)SEQ * SEQ);
    }

    // #6: V transpose
    {
        dim3 g(SEQ / 32, DMODEL / 32, BATCH);
        transpose_h<<<g, blk>>>(Vh, Vth);
    }

    // #7: softmax -> P single fp16
    softmax_kernel<<<MTOT, blk>>>(S, Ph);

    // #8: ctx = P Vt^T -> single fp16  (K = SEQ)
    {
        dim3 grid(DMODEL / 256, SEQ / 128, BATCH);
        hgemm<2><<<grid, blk, HG_SMEM>>>(Ph, Vth, nullptr, Ch,
                                         SEQ, DMODEL, 1.f,
                                         (size_t)SEQ * SEQ,
                                         (size_t)DMODEL * SEQ,
                                         (size_t)SEQ * DMODEL);
    }

    // #9: out = ctx wo^T (fp32)
    {
        dim3 grid(DMODEL / 256, MTOT / 128, 1);
        hgemm<0><<<grid, blk, HG_SMEM>>>(Ch, wh + 3 * WSTR, out, nullptr,
                                         DMODEL, DMODEL, 1.f, 0, 0, 0);
    }
}